// round 16
// baseline (speedup 1.0000x reference)
#include <cuda_runtime.h>
#include <cuda_fp16.h>
#include <stdint.h>
#include <math.h>

// BN scale: 1/sqrt(1 + 1e-5)
#define BNS 0.9999950000374997f

#define DD      200
#define NTOT_MX 50006
#define H_MX    100000
#define NE_MX   600000
#define B_MX    2048
#define NR_MX   2048
#define CPITCH  1408      // EP row pitch (halves)
#define FEATK   39600     // 200 * 198
#define MROWS   (B_MX * 198)   // im2col rows
#define EP_SMEM (13 * 1024 * 4 + 2 * 1056 * 4)   // 61696 B

// ---------------- static device scratch ----------------------------------
__device__ __align__(128) float  g_T[200 * 200];
__device__ __align__(128) float  g_U[1200 * 200];
__device__ __align__(128) __half g_combh[200 * CPITCH];
__device__ __align__(128) __half g_Wcat[200 * 400];   // [0.5*T | w_rel] fp16
__device__ __align__(128) __half g_RO[(size_t)NR_MX * 400]; // [RW | outR] fp16
__device__ __align__(128) __half g_Eh[(size_t)NTOT_MX * 200];
__device__ __align__(128) __half g_Rh[(size_t)NR_MX * 200];
__device__ __align__(128) __half g_fcwh[(size_t)FEATK * 200]; // permuted (p,nf)
__device__ __align__(128) __half g_EP[(size_t)NTOT_MX * CPITCH];
__device__ __align__(128) __half g_hembW[(size_t)H_MX * 200];
__device__ __align__(128) __half g_agg[(size_t)NTOT_MX * 200];   // fp16 RED target
__device__ __align__(128) __half g_outEh[(size_t)NTOT_MX * 200]; // fp16 outE
__device__ __align__(128) __half g_X[(size_t)MROWS * 32];    // im2col, K pad 32
__device__ __align__(128) __half g_convW[32 * 200];          // conv W [k][nf]
__device__ __align__(128) float  g_epiG[256];
__device__ __align__(128) float  g_epiB[256];
__device__ __align__(128) __half g_Y[(size_t)B_MX * FEATK];  // (b)(p*200+nf)
__device__ __align__(128) float  g_FCACC[(size_t)B_MX * 200];

// ---------------- helpers -------------------------------------------------
__device__ __forceinline__ unsigned pack2(float a, float b) {
    __half2 h = __floats2half2_rn(a, b);
    return *(unsigned*)&h;
}
__device__ __forceinline__ void red2(float* p, float x, float y) {
    asm volatile("red.global.add.v2.f32 [%0], {%1, %2};"
                 :: "l"(p), "f"(x), "f"(y) : "memory");
}
__device__ __forceinline__ float4 ld4(const float* p) {
    return *(const float4*)p;
}
__device__ __forceinline__ float4 ld4(const __half* p) {
    uint2 u = *(const uint2*)p;
    __half2 h0 = *(__half2*)&u.x;
    __half2 h1 = *(__half2*)&u.y;
    float2 a = __half22float2(h0);
    float2 b = __half22float2(h1);
    return make_float4(a.x, a.y, b.x, b.y);
}
__device__ __forceinline__ void store2(float* p, float x, float y) {
    *(float2*)p = make_float2(x, y);
}
__device__ __forceinline__ void store2(__half* p, float x, float y) {
    *(__half2*)p = __floats2half2_rn(x, y);
}
__device__ __forceinline__ uint4 ldA8(const float* p) {
    float4 x = *(const float4*)p;
    float4 y = *(const float4*)(p + 4);
    uint4 r;
    r.x = pack2(x.x, x.y); r.y = pack2(x.z, x.w);
    r.z = pack2(y.x, y.y); r.w = pack2(y.z, y.w);
    return r;
}
__device__ __forceinline__ uint4 ldA8(const __half* p) {
    return *(const uint4*)p;
}
__device__ __forceinline__ unsigned ldA2(const float* p) {
    float2 v = *(const float2*)p;
    return pack2(v.x, v.y);
}
__device__ __forceinline__ unsigned ldA2(const __half* p) {
    return *(const unsigned*)p;
}
__device__ __forceinline__ float ldS(const float* p) { return *p; }
__device__ __forceinline__ float ldS(const __half* p) { return __half2float(*p); }

__device__ __forceinline__ void loadBfrag(const float* q, int ldb, unsigned* bS) {
    float2 r0a = *(const float2*)(q);
    float2 r0b = *(const float2*)(q + (size_t)ldb);
    float2 r1a = *(const float2*)(q + (size_t)8 * ldb);
    float2 r1b = *(const float2*)(q + (size_t)9 * ldb);
    bS[0] = pack2(r0a.x, r0b.x);
    bS[1] = pack2(r1a.x, r1b.x);
    bS[2] = pack2(r0a.y, r0b.y);
    bS[3] = pack2(r1a.y, r1b.y);
}
__device__ __forceinline__ void loadBfrag(const __half* q, int ldb, unsigned* bS) {
    __half2 r0a = *(const __half2*)(q);
    __half2 r0b = *(const __half2*)(q + (size_t)ldb);
    __half2 r1a = *(const __half2*)(q + (size_t)8 * ldb);
    __half2 r1b = *(const __half2*)(q + (size_t)9 * ldb);
    __half2 t;
    t = __halves2half2(__low2half(r0a),  __low2half(r0b));  bS[0] = *(unsigned*)&t;
    t = __halves2half2(__low2half(r1a),  __low2half(r1b));  bS[1] = *(unsigned*)&t;
    t = __halves2half2(__high2half(r0a), __high2half(r0b)); bS[2] = *(unsigned*)&t;
    t = __halves2half2(__high2half(r1a), __high2half(r1b)); bS[3] = *(unsigned*)&t;
}

__device__ __forceinline__ void mma_f16_k16(float* c, const unsigned* a,
                                            const unsigned* b) {
    asm volatile(
        "mma.sync.aligned.m16n8k16.row.col.f32.f16.f16.f32 "
        "{%0,%1,%2,%3}, {%4,%5,%6,%7}, {%8,%9}, {%0,%1,%2,%3};"
        : "+f"(c[0]), "+f"(c[1]), "+f"(c[2]), "+f"(c[3])
        : "r"(a[0]), "r"(a[1]), "r"(a[2]), "r"(a[3]), "r"(b[0]), "r"(b[1]));
}
__device__ __forceinline__ void mma_f16_k8(float* c, const unsigned* a,
                                           unsigned b) {
    asm volatile(
        "mma.sync.aligned.m16n8k8.row.col.f32.f16.f16.f32 "
        "{%0,%1,%2,%3}, {%4,%5}, {%6}, {%0,%1,%2,%3};"
        : "+f"(c[0]), "+f"(c[1]), "+f"(c[2]), "+f"(c[3])
        : "r"(a[0]), "r"(a[1]), "r"(b));
}

// =========================================================================
// EP-specialized GEMM: EP(M x 1400 f16, pitch CPITCH) = Eh(M x 200) @ comb
// =========================================================================
__global__ void __launch_bounds__(256, 2) ep_gemm_k(
    const __half* __restrict__ A, const __half* __restrict__ B,
    __half* __restrict__ C, int M)
{
    extern __shared__ __align__(16) unsigned smemE[];
    unsigned* Asm = smemE;               // 13 * 1024
    unsigned* Bsm = smemE + 13 * 1024;   // 2 * 1056

    const int tid  = threadIdx.x;
    const int lane = tid & 31;
    const int warp = tid >> 5;
    const int wm = warp >> 2;
    const int wn = warp & 3;
    const int m0 = blockIdx.y * 128;
    const int ntB = blockIdx.x * 6;
    const int ntE = min(ntB + 6, 11);

    const int am    = tid >> 1;
    const int khalf = tid & 1;
    const bool aVal = (m0 + am) < M;
    const int amf  = am >> 4;
    const int ar   = am & 15;
    const int arl  = ar & 7;
    const int aReg = (khalf << 1) | (ar >> 3);
#pragma unroll
    for (int ch = 0; ch < 13; ch++) {
        int kk = ch * 16 + khalf * 8;
        uint4 v = make_uint4(0u, 0u, 0u, 0u);
        if (aVal && kk < 200)
            v = *(const uint4*)(A + (size_t)(m0 + am) * 200 + kk);
        unsigned aw[4] = {v.x, v.y, v.z, v.w};
#pragma unroll
        for (int jj = 0; jj < 4; jj++) {
            int c_   = arl * 4 + jj;
            int phys = c_ ^ ((c_ >> 3) & 3);
            Asm[ch * 1024 + amf * 128 + phys * 4 + aReg] = aw[jj];
        }
    }
    __syncthreads();

    const int bkp = (tid >> 6) & 3;
    const int bn0 = (tid & 63) << 1;
    const int bnf = bn0 >> 3;
    const int bLane0 = (bn0 & 7) * 4 + bkp;
    const int lphys = lane ^ ((lane >> 3) & 3);
    const __half2 hz = __floats2half2_rn(0.f, 0.f);

    for (int nt = ntB; nt < ntE; nt++) {
        const int n0 = nt * 128;
        const int col = n0 + bn0;
        const bool cv = col < 1400;

        float acc[4][4][4];
#pragma unroll
        for (int i = 0; i < 4; i++)
#pragma unroll
            for (int j = 0; j < 4; j++)
#pragma unroll
                for (int q = 0; q < 4; q++) acc[i][j][q] = 0.f;

        unsigned bS0[4], bS1[4];

#define EP_LOADB(CH, BR)                                                     \
    {                                                                        \
        int k0r = (CH) * 16 + 2 * bkp;                                       \
        __half2 r0a = (cv && k0r     < 200) ?                                \
            *(const __half2*)(B + (size_t)(k0r)     * CPITCH + col) : hz;    \
        __half2 r0b = (cv && k0r + 1 < 200) ?                                \
            *(const __half2*)(B + (size_t)(k0r + 1) * CPITCH + col) : hz;    \
        __half2 r1a = (cv && k0r + 8 < 200) ?                                \
            *(const __half2*)(B + (size_t)(k0r + 8) * CPITCH + col) : hz;    \
        __half2 r1b = (cv && k0r + 9 < 200) ?                                \
            *(const __half2*)(B + (size_t)(k0r + 9) * CPITCH + col) : hz;    \
        __half2 t_;                                                          \
        t_ = __halves2half2(__low2half(r0a),  __low2half(r0b));              \
        BR[0] = *(unsigned*)&t_;                                             \
        t_ = __halves2half2(__low2half(r1a),  __low2half(r1b));              \
        BR[1] = *(unsigned*)&t_;                                             \
        t_ = __halves2half2(__high2half(r0a), __high2half(r0b));             \
        BR[2] = *(unsigned*)&t_;                                             \
        t_ = __halves2half2(__high2half(r1a), __high2half(r1b));             \
        BR[3] = *(unsigned*)&t_;                                             \
    }
#define EP_STOREB(BUF, BR)                                                   \
    {                                                                        \
        Bsm[(BUF) * 1056 + bnf * 66 + bLane0 * 2 + 0]       = BR[0];         \
        Bsm[(BUF) * 1056 + bnf * 66 + bLane0 * 2 + 1]       = BR[1];         \
        Bsm[(BUF) * 1056 + bnf * 66 + (bLane0 + 4) * 2 + 0] = BR[2];         \
        Bsm[(BUF) * 1056 + bnf * 66 + (bLane0 + 4) * 2 + 1] = BR[3];         \
    }
#define EP_CONSUME(BUF, CH)                                                  \
    {                                                                        \
        unsigned af[4][4], bf[4][2];                                         \
        _Pragma("unroll")                                                    \
        for (int mf = 0; mf < 4; mf++) {                                     \
            uint4 t = *(const uint4*)&Asm[(CH) * 1024 +                      \
                                          (wm * 4 + mf) * 128 + lphys * 4];  \
            af[mf][0] = t.x; af[mf][1] = t.y;                                \
            af[mf][2] = t.z; af[mf][3] = t.w;                                \
        }                                                                    \
        _Pragma("unroll")                                                    \
        for (int nf = 0; nf < 4; nf++) {                                     \
            uint2 t = *(const uint2*)&Bsm[(BUF) * 1056 +                     \
                                          (wn * 4 + nf) * 66 + lane * 2];    \
            bf[nf][0] = t.x; bf[nf][1] = t.y;                                \
        }                                                                    \
        _Pragma("unroll")                                                    \
        for (int mf = 0; mf < 4; mf++)                                       \
            _Pragma("unroll")                                                \
            for (int nf = 0; nf < 4; nf++)                                   \
                mma_f16_k16(acc[mf][nf], af[mf], bf[nf]);                    \
    }

        EP_LOADB(0, bS0);
        EP_STOREB(0, bS0);
        EP_LOADB(1, bS1);
        __syncthreads();
        int it = 0;
        for (;;) {
            if (it + 2 < 13) EP_LOADB(it + 2, bS0);
            EP_CONSUME(0, it);
            if (++it >= 13) break;
            EP_STOREB(1, bS1);
            __syncthreads();
            if (it + 2 < 13) EP_LOADB(it + 2, bS1);
            EP_CONSUME(1, it);
            if (++it >= 13) break;
            EP_STOREB(0, bS0);
            __syncthreads();
        }
#undef EP_LOADB
#undef EP_STOREB
#undef EP_CONSUME

#pragma unroll
        for (int mf = 0; mf < 4; mf++) {
#pragma unroll
            for (int nf = 0; nf < 4; nf++) {
                int row = m0 + wm * 64 + mf * 16 + (lane >> 2);
                int cc  = n0 + wn * 32 + nf * 8 + ((lane & 3) << 1);
                if (cc >= 1400) continue;
                __half* p = C + (size_t)row * CPITCH + cc;
                if (row < M)
                    store2(p, acc[mf][nf][0], acc[mf][nf][1]);
                if (row + 8 < M)
                    store2(p + (size_t)8 * CPITCH,
                           acc[mf][nf][2], acc[mf][nf][3]);
            }
        }
        __syncthreads();
    }
}

// =========================================================================
// fp16 tensor-core GEMM (fp32 accum): C = A(MxK,row) @ B(KxN,row)
// MODE 0: store. MODE 1: red.global. MODE 2: relu(acc*epiG+epiB).
// (R13 mainloop — no per-fragment branches.)
// =========================================================================
template <class AT, class BT, class CT, int MODE>
__global__ void __launch_bounds__(256, 2) hmma_gemm_k(
    const AT* __restrict__ A, const BT* __restrict__ B,
    CT* __restrict__ C, int M, int N, int K,
    int lda, int ldb, int ldc, float alpha, int kChunk,
    const float* __restrict__ epiG, const float* __restrict__ epiB)
{
    __shared__ __align__(16) unsigned As[2][1024];
    __shared__ __align__(16) unsigned Bs[2][1056];

    const int tid  = threadIdx.x;
    const int lane = tid & 31;
    const int warp = tid >> 5;
    const int wm = warp >> 2;
    const int wn = warp & 3;
    const int m0 = blockIdx.y * 128;
    const int n0b = blockIdx.x * 128;

    const int kBegin = blockIdx.z * kChunk;
    const int kEnd   = min(kBegin + kChunk, K);
    const int iters  = (kEnd - kBegin) >> 4;
    const bool tail8 = ((kEnd - kBegin) & 8) != 0;

    const int am    = tid >> 1;
    const int khalf = tid & 1;
    const bool aVal = (m0 + am) < M;
    const AT* Ap = A + (size_t)(m0 + am) * lda + kBegin + khalf * 8;
    const int amf  = am >> 4;
    const int ar   = am & 15;
    const int arl  = ar & 7;
    const int aReg = (khalf << 1) | (ar >> 3);

    const int bkp = (tid >> 6) & 3;
    const int bn0 = (tid & 63) << 1;
    const bool bVal = (n0b + bn0) < N;
    const BT* Bp = B + (size_t)(kBegin + 2 * bkp) * ldb + n0b + bn0;
    const int bnf = bn0 >> 3;
    const int bLane0 = (bn0 & 7) * 4 + bkp;

    float acc[4][4][4];
#pragma unroll
    for (int i = 0; i < 4; i++)
#pragma unroll
        for (int j = 0; j < 4; j++)
#pragma unroll
            for (int q = 0; q < 4; q++) acc[i][j][q] = 0.f;

    uint4 aS0, aS1;
    unsigned bS0[4], bS1[4];
    const int lphys = lane ^ ((lane >> 3) & 3);

#define LOADR(IT, AR, BR)                                                    \
    {                                                                        \
        AR = aVal ? ldA8(Ap + ((IT) << 4)) : make_uint4(0u, 0u, 0u, 0u);     \
        if (bVal) loadBfrag(Bp + (size_t)((IT) << 4) * ldb, ldb, BR);        \
        else { BR[0] = BR[1] = BR[2] = BR[3] = 0u; }                         \
    }
#define STORER(BUF, AR, BR)                                                  \
    {                                                                        \
        unsigned aw[4] = {AR.x, AR.y, AR.z, AR.w};                           \
        _Pragma("unroll")                                                    \
        for (int jj = 0; jj < 4; jj++) {                                     \
            int c_   = arl * 4 + jj;                                         \
            int phys = c_ ^ ((c_ >> 3) & 3);                                 \
            As[BUF][amf * 128 + phys * 4 + aReg] = aw[jj];                   \
        }                                                                    \
        Bs[BUF][bnf * 66 + bLane0 * 2 + 0]       = BR[0];                    \
        Bs[BUF][bnf * 66 + bLane0 * 2 + 1]       = BR[1];                    \
        Bs[BUF][bnf * 66 + (bLane0 + 4) * 2 + 0] = BR[2];                    \
        Bs[BUF][bnf * 66 + (bLane0 + 4) * 2 + 1] = BR[3];                    \
    }
#define CONSUME(BUF)                                                         \
    {                                                                        \
        unsigned af[4][4], bf[4][2];                                         \
        _Pragma("unroll")                                                    \
        for (int mf = 0; mf < 4; mf++) {                                     \
            uint4 t = *(const uint4*)&As[BUF][(wm * 4 + mf) * 128 + lphys * 4]; \
            af[mf][0] = t.x; af[mf][1] = t.y; af[mf][2] = t.z; af[mf][3] = t.w; \
        }                                                                    \
        _Pragma("unroll")                                                    \
        for (int nf = 0; nf < 4; nf++) {                                     \
            uint2 t = *(const uint2*)&Bs[BUF][(wn * 4 + nf) * 66 + lane * 2]; \
            bf[nf][0] = t.x; bf[nf][1] = t.y;                                \
        }                                                                    \
        _Pragma("unroll")                                                    \
        for (int mf = 0; mf < 4; mf++)                                       \
            _Pragma("unroll")                                                \
            for (int nf = 0; nf < 4; nf++)                                   \
                mma_f16_k16(acc[mf][nf], af[mf], bf[nf]);                    \
    }

    if (iters > 0) {
        LOADR(0, aS0, bS0);
        STORER(0, aS0, bS0);
        if (iters > 1) LOADR(1, aS1, bS1);
        __syncthreads();
        int it = 0;
        for (;;) {
            if (it + 2 < iters) LOADR(it + 2, aS0, bS0);
            CONSUME(0);
            if (++it >= iters) break;
            STORER(1, aS1, bS1);
            __syncthreads();
            if (it + 2 < iters) LOADR(it + 2, aS1, bS1);
            CONSUME(1);
            if (++it >= iters) break;
            STORER(0, aS0, bS0);
            __syncthreads();
        }
    }
#undef LOADR
#undef STORER
#undef CONSUME

    if (tail8) {
        const int kT = kEnd - 8;
        const int kOff = kT + 2 * (lane & 3);
        unsigned bt[4];
#pragma unroll
        for (int nf = 0; nf < 4; nf++) {
            int col = n0b + wn * 32 + nf * 8 + (lane >> 2);
            float v0 = 0.f, v1 = 0.f;
            if (col < N) {
                v0 = ldS(B + (size_t)kOff * ldb + col);
                v1 = ldS(B + (size_t)(kOff + 1) * ldb + col);
            }
            bt[nf] = pack2(v0, v1);
        }
#pragma unroll
        for (int mf = 0; mf < 4; mf++) {
            int r0 = m0 + wm * 64 + mf * 16 + (lane >> 2);
            unsigned at[2];
            at[0] = (r0 < M)     ? ldA2(A + (size_t)r0 * lda + kOff)       : 0u;
            at[1] = (r0 + 8 < M) ? ldA2(A + (size_t)(r0 + 8) * lda + kOff) : 0u;
#pragma unroll
            for (int nf = 0; nf < 4; nf++)
                mma_f16_k8(acc[mf][nf], at, bt[nf]);
        }
    }

#pragma unroll
    for (int mf = 0; mf < 4; mf++) {
#pragma unroll
        for (int nf = 0; nf < 4; nf++) {
            int row = m0 + wm * 64 + mf * 16 + (lane >> 2);
            int col = n0b + wn * 32 + nf * 8 + ((lane & 3) << 1);
            if (col >= N) continue;
            CT* p = C + (size_t)row * ldc + col;
            float g0 = 0.f, g1 = 0.f, bb0 = 0.f, bb1 = 0.f;
            if (MODE == 2) {
                g0 = epiG[col]; g1 = epiG[col + 1];
                bb0 = epiB[col]; bb1 = epiB[col + 1];
            }
            if (row < M) {
                if (MODE == 1)
                    red2((float*)(void*)p,
                         alpha * acc[mf][nf][0], alpha * acc[mf][nf][1]);
                else if (MODE == 2)
                    store2(p, fmaxf(acc[mf][nf][0] * g0 + bb0, 0.f),
                              fmaxf(acc[mf][nf][1] * g1 + bb1, 0.f));
                else
                    store2(p, alpha * acc[mf][nf][0], alpha * acc[mf][nf][1]);
            }
            if (row + 8 < M) {
                CT* q = p + (size_t)8 * ldc;
                if (MODE == 1)
                    red2((float*)(void*)q,
                         alpha * acc[mf][nf][2], alpha * acc[mf][nf][3]);
                else if (MODE == 2)
                    store2(q, fmaxf(acc[mf][nf][2] * g0 + bb0, 0.f),
                              fmaxf(acc[mf][nf][3] * g1 + bb1, 0.f));
                else
                    store2(q, alpha * acc[mf][nf][2], alpha * acc[mf][nf][3]);
            }
        }
    }
}

// ---------------- SIMT SGEMM (exact fp32) for the weight precompute ------
template <bool ATOMIC>
__global__ void __launch_bounds__(256) sgemm_k(
    const float* __restrict__ A, const float* __restrict__ B,
    float* __restrict__ C, int M, int Ncols, int K,
    int lda, int ldb, int ldc, float alpha, int kChunk)
{
    __shared__ float As[8][128];
    __shared__ float Bs[8][128];

    const int tid = threadIdx.x;
    const int tx = tid & 15;
    const int ty = tid >> 4;
    const int m0 = blockIdx.y * 128;
    const int n0 = blockIdx.x * 128;

    int kBegin = blockIdx.z * kChunk;
    int kEnd = kBegin + kChunk;
    if (kEnd > K) kEnd = K;

    const int aRow = tid >> 1;
    const int aK4  = (tid & 1) << 2;
    const int bRow = tid >> 5;
    const int bCol = (tid & 31) << 2;

    float acc[8][8];
#pragma unroll
    for (int i = 0; i < 8; i++)
#pragma unroll
        for (int j = 0; j < 8; j++) acc[i][j] = 0.f;

    for (int k0 = kBegin; k0 < kEnd; k0 += 8) {
        float4 av = make_float4(0.f, 0.f, 0.f, 0.f);
        if (m0 + aRow < M)
            av = *(const float4*)(A + (size_t)(m0 + aRow) * lda + (k0 + aK4));
        As[aK4 + 0][aRow] = av.x;
        As[aK4 + 1][aRow] = av.y;
        As[aK4 + 2][aRow] = av.z;
        As[aK4 + 3][aRow] = av.w;

        float4 bv = make_float4(0.f, 0.f, 0.f, 0.f);
        if (n0 + bCol < Ncols)
            bv = *(const float4*)(B + (size_t)(k0 + bRow) * ldb + (n0 + bCol));
        *(float4*)&Bs[bRow][bCol] = bv;

        __syncthreads();
#pragma unroll
        for (int kk = 0; kk < 8; kk++) {
            float ar[8], br[8];
#pragma unroll
            for (int i = 0; i < 8; i++) ar[i] = As[kk][ty * 8 + i];
#pragma unroll
            for (int j = 0; j < 8; j++) br[j] = Bs[kk][tx * 8 + j];
#pragma unroll
            for (int i = 0; i < 8; i++)
#pragma unroll
                for (int j = 0; j < 8; j++)
                    acc[i][j] = fmaf(ar[i], br[j], acc[i][j]);
        }
        __syncthreads();
    }

#pragma unroll
    for (int i = 0; i < 8; i++) {
        int m = m0 + ty * 8 + i;
        if (m >= M) continue;
        if (ATOMIC) {
#pragma unroll
            for (int jj = 0; jj < 8; jj += 2) {
                int n = n0 + tx * 8 + jj;
                if (n < Ncols)
                    red2(C + (size_t)m * ldc + n,
                         alpha * acc[i][jj], alpha * acc[i][jj + 1]);
            }
        } else {
#pragma unroll
            for (int jj = 0; jj < 8; jj += 4) {
                int n = n0 + tx * 8 + jj;
                if (n < Ncols) {
                    float4 v = make_float4(alpha * acc[i][jj + 0],
                                           alpha * acc[i][jj + 1],
                                           alpha * acc[i][jj + 2],
                                           alpha * acc[i][jj + 3]);
                    *(float4*)(C + (size_t)m * ldc + n) = v;
                }
            }
        }
    }
}

// ---------------- merged prep: f2h(E) | permfcw | f2h(R) | convprep ------
__global__ void __launch_bounds__(256) prep_k(
    const float* __restrict__ E, const float* __restrict__ R,
    const float* __restrict__ fc_w,
    const float* __restrict__ conv_w, const float* __restrict__ conv_b,
    const float* __restrict__ bn1_g, const float* __restrict__ bn1_b,
    int n4e, int n4r, int bA, int bB, int bC)
{
    int b = blockIdx.x;
    int t = threadIdx.x;
    if (b < bA) {
        int i = b * 256 + t;
        if (i < n4e) {
            float4 v = ((const float4*)E)[i];
            uint2 o;
            o.x = pack2(v.x, v.y);
            o.y = pack2(v.z, v.w);
            ((uint2*)g_Eh)[i] = o;
        }
    } else if (b < bA + bB) {
        int idx = (b - bA) * 256 + t;
        if (idx < FEATK * 50) {
            int r = idx / 50;
            int c = idx - r * 50;
            int p  = r / 200;
            int nf = r - p * 200;
            float4 v = *(const float4*)(fc_w + ((size_t)nf * 198 + p) * 200 + c * 4);
            uint2 o;
            o.x = pack2(v.x, v.y);
            o.y = pack2(v.z, v.w);
            *(uint2*)(g_fcwh + (size_t)r * 200 + c * 4) = o;
        }
    } else if (b < bA + bB + bC) {
        int i = (b - bA - bB) * 256 + t;
        if (i < n4r) {
            float4 v = ((const float4*)R)[i];
            uint2 o;
            o.x = pack2(v.x, v.y);
            o.y = pack2(v.z, v.w);
            ((uint2*)g_Rh)[i] = o;
        }
    } else {
        int idx = (b - bA - bB - bC) * 256 + t;
        if (idx < 32 * 200) {
            int k  = idx / 200;
            int nf = idx - k * 200;
            float v = (k < 21) ? conv_w[nf * 21 + k] : 0.f;
            g_convW[k * 200 + nf] = __float2half(v);
        }
        if (idx < 256) {
            if (idx < 200) {
                float g = bn1_g[idx] * BNS;
                g_epiG[idx] = g;
                g_epiB[idx] = conv_b[idx] * g + bn1_b[idx];
            } else {
                g_epiG[idx] = 0.f;
                g_epiB[idx] = 0.f;
            }
        }
    }
}

// ---------------- merged comb (200x1400 fp16) + Wcat (200x400 fp16) ------
__global__ void __launch_bounds__(256) combwcat_k(
    const float* __restrict__ E, const float* __restrict__ w_addpos,
    const float* __restrict__ w_rel, int ent, int bComb)
{
    int b = blockIdx.x;
    int t = threadIdx.x;
    if (b < bComb) {
        int idx = b * 256 + t;
        if (idx < 200 * 1400) {
            int i = idx / 1400;
            int c = idx - i * 1400;
            float v;
            if (c < 1200) {
                int k = c / 200;
                int j = c - k * 200;
                v = 0.5f * E[(size_t)(ent + k) * DD + i] *
                    g_U[(size_t)(k * 200 + i) * 200 + j];
            } else {
                v = w_addpos[(size_t)(200 + i) * 200 + (c - 1200)];
            }
            g_combh[(size_t)i * CPITCH + c] = __float2half(v);
        }
    } else {
        int idx = (b - bComb) * 256 + t;
        if (idx < 200 * 400) {
            int i = idx / 400;
            int c = idx - i * 400;
            float v = (c < 200) ? 0.5f * g_T[i * 200 + c]
                                : w_rel[(size_t)i * 200 + (c - 200)];
            g_Wcat[idx] = __float2half(v);
        }
    }
}

// ---------------- hembW[h] = RO[he0,0:200] + sum_k EP[he_k+1, k*200:] ----
__global__ void hembw_k(const int* __restrict__ he, int H)
{
    int t = blockIdx.x * 256 + threadIdx.x;
    int h = t / 50;
    int c = t - h * 50;
    if (h >= H) return;
    const int* row = he + (size_t)h * 7;
    int r = row[0];
    float4 acc = ld4(g_RO + (size_t)r * 400 + c * 4);
#pragma unroll
    for (int k = 0; k < 6; k++) {
        int e = row[1 + k];
        float4 v = ld4(g_EP + (size_t)e * CPITCH + k * 200 + c * 4);
        acc.x += v.x; acc.y += v.y; acc.z += v.z; acc.w += v.w;
    }
    __half* dst = g_hembW + (size_t)h * 200 + c * 4;
    ((__half2*)dst)[0] = __floats2half2_rn(acc.x, acc.y);
    ((__half2*)dst)[1] = __floats2half2_rn(acc.z, acc.w);
}

// ---------------- per-edge scatter (fp16x2 vector RED) --------------------
__global__ void edge_k(const int* __restrict__ ei,
                       const int* __restrict__ et, int NEdge)
{
    int t = blockIdx.x * 256 + threadIdx.x;
    int e = t / 25;
    int c = t - e * 25;
    if (e >= NEdge) return;
    int seg  = ei[e];
    int gidx = ei[NEdge + e];
    int h    = et[e];
    uint4 ua = *(const uint4*)(g_hembW + (size_t)h * 200 + c * 8);
    uint4 ub = *(const uint4*)(g_EP + (size_t)gidx * CPITCH + 1200 + c * 8);
    unsigned r[4];
#pragma unroll
    for (int j = 0; j < 4; j++) {
        __half2 x = ((__half2*)&ua)[j];
        __half2 y = ((__half2*)&ub)[j];
        __half2 s = __hadd2(x, y);
        r[j] = *(unsigned*)&s;
    }
    __half* p = g_agg + (size_t)seg * 200 + c * 8;
    asm volatile("red.global.add.noftz.v4.f16x2 [%0], {%1, %2, %3, %4};"
                 :: "l"(p), "r"(r[0]), "r"(r[1]), "r"(r[2]), "r"(r[3])
                 : "memory");
}

// ---------------- outE = tanh(bn(0.5*agg + 0.5*E)) -> fp16 ---------------
__global__ void oute_k(const float* __restrict__ E,
                       const float* __restrict__ g,
                       const float* __restrict__ bb, int Ntot)
{
    int t = blockIdx.x * 256 + threadIdx.x;
    int n = t / 50;
    int c = t - n * 50;
    if (n >= Ntot) return;
    size_t off = (size_t)n * 200 + c * 4;
    float4 e = *(const float4*)(E + off);
    float4 a = ld4(g_agg + off);
    int d = c * 4;
    float4 o;
    o.x = tanhf(0.5f * (a.x + e.x) * (g[d + 0] * BNS) + bb[d + 0]);
    o.y = tanhf(0.5f * (a.y + e.y) * (g[d + 1] * BNS) + bb[d + 1]);
    o.z = tanhf(0.5f * (a.z + e.z) * (g[d + 2] * BNS) + bb[d + 2]);
    o.w = tanhf(0.5f * (a.w + e.w) * (g[d + 3] * BNS) + bb[d + 3]);
    __half* dst = g_outEh + off;
    ((__half2*)dst)[0] = __floats2half2_rn(o.x, o.y);
    ((__half2*)dst)[1] = __floats2half2_rn(o.z, o.w);
}

// ---------------- build im2col X rows (fp16): one block per batch b ------
struct IdxPtrs { const int* p[6]; };

__global__ void __launch_bounds__(256) buildX_k(
    const float* __restrict__ ms, const int* __restrict__ r_idx, IdxPtrs ip,
    const float* __restrict__ bn0_g, const float* __restrict__ bn0_b,
    int ent)
{
    __shared__ float xs[7][204];

    int b = blockIdx.x;
    int t = threadIdx.x;

    float g0 = bn0_g[0] * BNS;
    float b0 = bn0_b[0];
    int ri = r_idx[b];

    for (int idx = t; idx < 1400; idx += 256) {
        int i = idx / 200;
        int d = idx - i * 200;
        float v;
        if (i == 0) {
            v = __half2float(g_RO[(size_t)ri * 400 + 200 + d]);
        } else {
            int k = i - 1;
            int eidx = ip.p[k][b];
            v = __half2float(g_outEh[(size_t)eidx * 200 + d]) *
                __half2float(g_outEh[(size_t)(ent + k) * 200 + d]) *
                ms[b * 6 + k];
        }
        xs[i][d] = v * g0 + b0;
    }
    __syncthreads();

    if (t < 198) {
        int p = t;
        unsigned w[16];
        float x[7][3];
#pragma unroll
        for (int i = 0; i < 7; i++)
#pragma unroll
            for (int q = 0; q < 3; q++) x[i][q] = xs[i][p + q];
        w[0]  = pack2(x[0][0], x[0][1]);
        w[1]  = pack2(x[0][2], x[1][0]);
        w[2]  = pack2(x[1][1], x[1][2]);
        w[3]  = pack2(x[2][0], x[2][1]);
        w[4]  = pack2(x[2][2], x[3][0]);
        w[5]  = pack2(x[3][1], x[3][2]);
        w[6]  = pack2(x[4][0], x[4][1]);
        w[7]  = pack2(x[4][2], x[5][0]);
        w[8]  = pack2(x[5][1], x[5][2]);
        w[9]  = pack2(x[6][0], x[6][1]);
        w[10] = pack2(x[6][2], 0.f);
#pragma unroll
        for (int q = 11; q < 16; q++) w[q] = 0u;
        uint4* dst = (uint4*)(g_X + ((size_t)b * 198 + p) * 32);
        dst[0] = make_uint4(w[0], w[1], w[2], w[3]);
        dst[1] = make_uint4(w[4], w[5], w[6], w[7]);
        dst[2] = make_uint4(w[8], w[9], w[10], w[11]);
        dst[3] = make_uint4(w[12], w[13], w[14], w[15]);
    }
}

// ---------------- final: relu(bn2(fc + bias)) row-sum -> out[b] ----------
__global__ void final_k(const float* __restrict__ fc_b,
                        const float* __restrict__ g,
                        const float* __restrict__ bb,
                        float* __restrict__ out, int B)
{
    int gt = blockIdx.x * 256 + threadIdx.x;
    int wb = gt >> 5;
    int lane = gt & 31;
    if (wb >= B) return;
    float s = 0.f;
    for (int d = lane; d < 200; d += 32) {
        float v = (g_FCACC[(size_t)wb * 200 + d] + fc_b[d]) * (g[d] * BNS) + bb[d];
        s += fmaxf(v, 0.f);
    }
#pragma unroll
    for (int o = 16; o; o >>= 1) s += __shfl_down_sync(0xffffffffu, s, o);
    if (lane == 0) out[wb] = s;
}

// ---------------- host orchestration ------------------------------------
extern "C" void kernel_launch(void* const* d_in, const int* in_sizes, int n_in,
                              void* d_out, int out_size)
{
    const float* E          = (const float*)d_in[0];
    const float* R          = (const float*)d_in[1];
    const float* w_alle     = (const float*)d_in[2];
    const float* w_addpos   = (const float*)d_in[3];
    const float* w_alleandr = (const float*)d_in[4];
    const float* w_rel      = (const float*)d_in[5];
    const float* conv_w     = (const float*)d_in[6];
    const float* conv_b     = (const float*)d_in[7];
    const float* fc_w       = (const float*)d_in[8];
    const float* fc_b       = (const float*)d_in[9];
    const float* bnmp_g     = (const float*)d_in[10];
    const float* bnmp_b     = (const float*)d_in[11];
    const float* bn0_g      = (const float*)d_in[12];
    const float* bn0_b      = (const float*)d_in[13];
    const float* bn1_g      = (const float*)d_in[14];
    const float* bn1_b      = (const float*)d_in[15];
    const float* bn2_g      = (const float*)d_in[16];
    const float* bn2_b      = (const float*)d_in[17];
    const float* ms         = (const float*)d_in[18];
    const int*   hyperedge  = (const int*)d_in[19];
    const int*   edge_index = (const int*)d_in[20];
    const int*   edge_type  = (const int*)d_in[21];
    const int*   r_idx      = (const int*)d_in[22];
    IdxPtrs ip;
    for (int k = 0; k < 6; k++) ip.p[k] = (const int*)d_in[23 + k];

    const int Ntot  = in_sizes[0] / DD;   // 50006
    const int ent   = Ntot - 6;
    const int NR    = in_sizes[1] / DD;   // 2000
    const int H     = in_sizes[19] / 7;   // 100000
    const int NEdge = in_sizes[21];       // 600000
    const int Bsz   = in_sizes[22];       // 2048

    float *pT, *pU, *pFC, *pG, *pB;
    __half *pComb, *pWcat, *pRO, *pEh, *pRh, *pFcw, *pEP, *pY, *pX, *pCW, *pAgg;
    cudaGetSymbolAddress((void**)&pT,    g_T);
    cudaGetSymbolAddress((void**)&pU,    g_U);
    cudaGetSymbolAddress((void**)&pComb, g_combh);
    cudaGetSymbolAddress((void**)&pWcat, g_Wcat);
    cudaGetSymbolAddress((void**)&pRO,   g_RO);
    cudaGetSymbolAddress((void**)&pEh,   g_Eh);
    cudaGetSymbolAddress((void**)&pRh,   g_Rh);
    cudaGetSymbolAddress((void**)&pFcw,  g_fcwh);
    cudaGetSymbolAddress((void**)&pEP,   g_EP);
    cudaGetSymbolAddress((void**)&pAgg,  g_agg);
    cudaGetSymbolAddress((void**)&pY,    g_Y);
    cudaGetSymbolAddress((void**)&pX,    g_X);
    cudaGetSymbolAddress((void**)&pCW,   g_convW);
    cudaGetSymbolAddress((void**)&pG,    g_epiG);
    cudaGetSymbolAddress((void**)&pB,    g_epiB);
    cudaGetSymbolAddress((void**)&pFC,   g_FCACC);

    cudaFuncSetAttribute(ep_gemm_k,
                         cudaFuncAttributeMaxDynamicSharedMemorySize,
                         EP_SMEM);

    cudaMemsetAsync(pT,   0, 200 * 200 * sizeof(float), 0);
    cudaMemsetAsync(pU,   0, 1200 * 200 * sizeof(float), 0);
    cudaMemsetAsync(pAgg, 0, (size_t)Ntot * 200 * sizeof(__half), 0);
    cudaMemsetAsync(pFC,  0, (size_t)Bsz * 200 * sizeof(float), 0);

    // merged prep: f2h(E) | permfcw | f2h(R) | convprep
    {
        int n4e = Ntot * DD / 4;
        int n4r = NR * DD / 4;
        int bA = (n4e + 255) / 256;
        int bB = (FEATK * 50 + 255) / 256;
        int bC = (n4r + 255) / 256;
        int bD = (32 * 200 + 255) / 256;
        prep_k<<<bA + bB + bC + bD, 256>>>(E, R, fc_w, conv_w, conv_b,
                                           bn1_g, bn1_b, n4e, n4r, bA, bB, bC);
    }

    // T = w_alleandr @ w_addpos_top  (exact fp32, split-K)
    sgemm_k<true><<<dim3(2, 2, 13), 256>>>(w_alleandr, w_addpos, pT,
                                           200, 200, 200, 200, 200, 200, 1.f, 16);
    // U = w_alle @ T  (exact fp32)
    sgemm_k<true><<<dim3(2, 10, 5), 256>>>(w_alle, pT, pU,
                                           1200, 200, 200, 200, 200, 200, 1.f, 40);
    // merged comb + Wcat (fp16)
    {
        int bComb = (200 * 1400 + 255) / 256;
        int bW    = (200 * 400 + 255) / 256;
        combwcat_k<<<bComb + bW, 256>>>(E, w_addpos, w_rel, ent, bComb);
    }
    // RO = Rh @ Wcat  (fp16 MMA, fp16 out; cols 0..199 = RW, 200..399 = outR)
    hmma_gemm_k<__half, __half, __half, 0>
        <<<dim3(4, (NR + 127) / 128, 1), 256>>>(
        pRh, pWcat, pRO, NR, 400, 200, 200, 400, 400, 1.f, 200,
        nullptr, nullptr);
    // EP = Eh @ comb  (A-resident fp16 MMA)
    ep_gemm_k<<<dim3(2, (Ntot + 127) / 128, 1), 256, EP_SMEM>>>(
        pEh, pComb, pEP, Ntot);
    // hembW: gather-sum per hyperedge (fp32 accum, fp16 store)
    hembw_k<<<(H * 50 + 255) / 256, 256>>>(hyperedge, H);
    // per-edge scatter (fp16 gathers, fp16x2 vector RED)
    edge_k<<<(NEdge * 25 + 255) / 256, 256>>>(edge_index, edge_type, NEdge);
    // outE = tanh(bn(0.5*agg + 0.5*E)) -> fp16
    oute_k<<<(Ntot * 50 + 255) / 256, 256>>>(E, bnmp_g, bnmp_b, Ntot);
    // im2col X (bn0 fused)
    buildX_k<<<Bsz, 256>>>(ms, r_idx, ip, bn0_g, bn0_b, ent);
    // Y = relu(conv(X) * g1 + bias)  (fp16 MMA, fused epilogue)
    hmma_gemm_k<__half, __half, __half, 2>
        <<<dim3(2, (Bsz * 198) / 128, 1), 256>>>(
        pX, pCW, pY, Bsz * 198, 200, 32, 32, 200, 200, 1.f, 32, pG, pB);
    // FCACC += Y @ fcwh  (fp16 MMA, split-K 15 x 2640 = 165 full k16 iters)
    hmma_gemm_k<__half, __half, float, 1>
        <<<dim3(2, (Bsz + 127) / 128, 15), 256>>>(
        pY, pFcw, pFC, Bsz, 200, FEATK, FEATK, 200, 200, 1.f, 2640,
        nullptr, nullptr);
    // out[b] = sum_d relu(bn2(FCACC + fc_b))
    final_k<<<(Bsz * 32 + 255) / 256, 256>>>(fc_b, bn2_g, bn2_b,
                                             (float*)d_out, Bsz);
}

// round 17
// speedup vs baseline: 1.0692x; 1.0692x over previous
#include <cuda_runtime.h>
#include <cuda_fp16.h>
#include <stdint.h>
#include <math.h>

// BN scale: 1/sqrt(1 + 1e-5)
#define BNS 0.9999950000374997f

#define DD      200
#define NTOT_MX 50006
#define H_MX    100000
#define NE_MX   600000
#define B_MX    2048
#define NR_MX   2048
#define CPITCH  1408      // EP row pitch (halves)
#define FEATK   39600     // 200 * 198
#define MROWS   (B_MX * 198)   // im2col rows
#define EP_SMEM (13 * 1024 * 4 + 2 * 1056 * 4)   // 61696 B

// ---------------- static device scratch ----------------------------------
__device__ __align__(128) float  g_T[200 * 200];
__device__ __align__(128) float  g_U[1200 * 200];
__device__ __align__(128) __half g_combh[200 * CPITCH];
__device__ __align__(128) __half g_Wcat[200 * 400];   // [0.5*T | w_rel] fp16
__device__ __align__(128) float  g_RO[(size_t)NR_MX * 400]; // [RW | outR]
__device__ __align__(128) __half g_Eh[(size_t)NTOT_MX * 200];
__device__ __align__(128) __half g_Rh[(size_t)NR_MX * 200];
__device__ __align__(128) __half g_fcwh[(size_t)FEATK * 200]; // permuted (p,nf)
__device__ __align__(128) __half g_EP[(size_t)NTOT_MX * CPITCH];
__device__ __align__(128) __half g_hembW[(size_t)H_MX * 200];
__device__ __align__(128) __half g_agg[(size_t)NTOT_MX * 200];   // fp16 RED target
__device__ __align__(128) __half g_X[(size_t)MROWS * 32];    // im2col, K pad 32
__device__ __align__(128) __half g_convW[32 * 200];          // conv W [k][nf]
__device__ __align__(128) float  g_epiG[256];
__device__ __align__(128) float  g_epiB[256];
__device__ __align__(128) __half g_Y[(size_t)B_MX * FEATK];  // (b)(p*200+nf)
__device__ __align__(128) float  g_FCACC[(size_t)B_MX * 200];

// ---------------- helpers -------------------------------------------------
__device__ __forceinline__ unsigned pack2(float a, float b) {
    __half2 h = __floats2half2_rn(a, b);
    return *(unsigned*)&h;
}
__device__ __forceinline__ void red2(float* p, float x, float y) {
    asm volatile("red.global.add.v2.f32 [%0], {%1, %2};"
                 :: "l"(p), "f"(x), "f"(y) : "memory");
}
__device__ __forceinline__ float4 ld4(const float* p) {
    return *(const float4*)p;
}
__device__ __forceinline__ float4 ld4(const __half* p) {
    uint2 u = *(const uint2*)p;
    __half2 h0 = *(__half2*)&u.x;
    __half2 h1 = *(__half2*)&u.y;
    float2 a = __half22float2(h0);
    float2 b = __half22float2(h1);
    return make_float4(a.x, a.y, b.x, b.y);
}
__device__ __forceinline__ void store2(float* p, float x, float y) {
    *(float2*)p = make_float2(x, y);
}
__device__ __forceinline__ void store2(__half* p, float x, float y) {
    *(__half2*)p = __floats2half2_rn(x, y);
}
__device__ __forceinline__ uint4 ldA8(const float* p) {
    float4 x = *(const float4*)p;
    float4 y = *(const float4*)(p + 4);
    uint4 r;
    r.x = pack2(x.x, x.y); r.y = pack2(x.z, x.w);
    r.z = pack2(y.x, y.y); r.w = pack2(y.z, y.w);
    return r;
}
__device__ __forceinline__ uint4 ldA8(const __half* p) {
    return *(const uint4*)p;
}
__device__ __forceinline__ unsigned ldA2(const float* p) {
    float2 v = *(const float2*)p;
    return pack2(v.x, v.y);
}
__device__ __forceinline__ unsigned ldA2(const __half* p) {
    return *(const unsigned*)p;
}
__device__ __forceinline__ float ldS(const float* p) { return *p; }
__device__ __forceinline__ float ldS(const __half* p) { return __half2float(*p); }

__device__ __forceinline__ void loadBfrag(const float* q, int ldb, unsigned* bS) {
    float2 r0a = *(const float2*)(q);
    float2 r0b = *(const float2*)(q + (size_t)ldb);
    float2 r1a = *(const float2*)(q + (size_t)8 * ldb);
    float2 r1b = *(const float2*)(q + (size_t)9 * ldb);
    bS[0] = pack2(r0a.x, r0b.x);
    bS[1] = pack2(r1a.x, r1b.x);
    bS[2] = pack2(r0a.y, r0b.y);
    bS[3] = pack2(r1a.y, r1b.y);
}
__device__ __forceinline__ void loadBfrag(const __half* q, int ldb, unsigned* bS) {
    __half2 r0a = *(const __half2*)(q);
    __half2 r0b = *(const __half2*)(q + (size_t)ldb);
    __half2 r1a = *(const __half2*)(q + (size_t)8 * ldb);
    __half2 r1b = *(const __half2*)(q + (size_t)9 * ldb);
    __half2 t;
    t = __halves2half2(__low2half(r0a),  __low2half(r0b));  bS[0] = *(unsigned*)&t;
    t = __halves2half2(__low2half(r1a),  __low2half(r1b));  bS[1] = *(unsigned*)&t;
    t = __halves2half2(__high2half(r0a), __high2half(r0b)); bS[2] = *(unsigned*)&t;
    t = __halves2half2(__high2half(r1a), __high2half(r1b)); bS[3] = *(unsigned*)&t;
}

__device__ __forceinline__ void mma_f16_k16(float* c, const unsigned* a,
                                            const unsigned* b) {
    asm volatile(
        "mma.sync.aligned.m16n8k16.row.col.f32.f16.f16.f32 "
        "{%0,%1,%2,%3}, {%4,%5,%6,%7}, {%8,%9}, {%0,%1,%2,%3};"
        : "+f"(c[0]), "+f"(c[1]), "+f"(c[2]), "+f"(c[3])
        : "r"(a[0]), "r"(a[1]), "r"(a[2]), "r"(a[3]), "r"(b[0]), "r"(b[1]));
}
__device__ __forceinline__ void mma_f16_k8(float* c, const unsigned* a,
                                           unsigned b) {
    asm volatile(
        "mma.sync.aligned.m16n8k8.row.col.f32.f16.f16.f32 "
        "{%0,%1,%2,%3}, {%4,%5}, {%6}, {%0,%1,%2,%3};"
        : "+f"(c[0]), "+f"(c[1]), "+f"(c[2]), "+f"(c[3])
        : "r"(a[0]), "r"(a[1]), "r"(b));
}

// =========================================================================
// EP-specialized GEMM: EP(M x 1400 f16, pitch CPITCH) = Eh(M x 200) @ comb
// =========================================================================
__global__ void __launch_bounds__(256, 2) ep_gemm_k(
    const __half* __restrict__ A, const __half* __restrict__ B,
    __half* __restrict__ C, int M)
{
    extern __shared__ __align__(16) unsigned smemE[];
    unsigned* Asm = smemE;               // 13 * 1024
    unsigned* Bsm = smemE + 13 * 1024;   // 2 * 1056

    const int tid  = threadIdx.x;
    const int lane = tid & 31;
    const int warp = tid >> 5;
    const int wm = warp >> 2;
    const int wn = warp & 3;
    const int m0 = blockIdx.y * 128;
    const int ntB = blockIdx.x * 6;
    const int ntE = min(ntB + 6, 11);

    const int am    = tid >> 1;
    const int khalf = tid & 1;
    const bool aVal = (m0 + am) < M;
    const int amf  = am >> 4;
    const int ar   = am & 15;
    const int arl  = ar & 7;
    const int aReg = (khalf << 1) | (ar >> 3);
#pragma unroll
    for (int ch = 0; ch < 13; ch++) {
        int kk = ch * 16 + khalf * 8;
        uint4 v = make_uint4(0u, 0u, 0u, 0u);
        if (aVal && kk < 200)
            v = *(const uint4*)(A + (size_t)(m0 + am) * 200 + kk);
        unsigned aw[4] = {v.x, v.y, v.z, v.w};
#pragma unroll
        for (int jj = 0; jj < 4; jj++) {
            int c_   = arl * 4 + jj;
            int phys = c_ ^ ((c_ >> 3) & 3);
            Asm[ch * 1024 + amf * 128 + phys * 4 + aReg] = aw[jj];
        }
    }
    __syncthreads();

    const int bkp = (tid >> 6) & 3;
    const int bn0 = (tid & 63) << 1;
    const int bnf = bn0 >> 3;
    const int bLane0 = (bn0 & 7) * 4 + bkp;
    const int lphys = lane ^ ((lane >> 3) & 3);
    const __half2 hz = __floats2half2_rn(0.f, 0.f);

    for (int nt = ntB; nt < ntE; nt++) {
        const int n0 = nt * 128;
        const int col = n0 + bn0;
        const bool cv = col < 1400;

        float acc[4][4][4];
#pragma unroll
        for (int i = 0; i < 4; i++)
#pragma unroll
            for (int j = 0; j < 4; j++)
#pragma unroll
                for (int q = 0; q < 4; q++) acc[i][j][q] = 0.f;

        unsigned bS0[4], bS1[4];

#define EP_LOADB(CH, BR)                                                     \
    {                                                                        \
        int k0r = (CH) * 16 + 2 * bkp;                                       \
        __half2 r0a = (cv && k0r     < 200) ?                                \
            *(const __half2*)(B + (size_t)(k0r)     * CPITCH + col) : hz;    \
        __half2 r0b = (cv && k0r + 1 < 200) ?                                \
            *(const __half2*)(B + (size_t)(k0r + 1) * CPITCH + col) : hz;    \
        __half2 r1a = (cv && k0r + 8 < 200) ?                                \
            *(const __half2*)(B + (size_t)(k0r + 8) * CPITCH + col) : hz;    \
        __half2 r1b = (cv && k0r + 9 < 200) ?                                \
            *(const __half2*)(B + (size_t)(k0r + 9) * CPITCH + col) : hz;    \
        __half2 t_;                                                          \
        t_ = __halves2half2(__low2half(r0a),  __low2half(r0b));              \
        BR[0] = *(unsigned*)&t_;                                             \
        t_ = __halves2half2(__low2half(r1a),  __low2half(r1b));              \
        BR[1] = *(unsigned*)&t_;                                             \
        t_ = __halves2half2(__high2half(r0a), __high2half(r0b));             \
        BR[2] = *(unsigned*)&t_;                                             \
        t_ = __halves2half2(__high2half(r1a), __high2half(r1b));             \
        BR[3] = *(unsigned*)&t_;                                             \
    }
#define EP_STOREB(BUF, BR)                                                   \
    {                                                                        \
        Bsm[(BUF) * 1056 + bnf * 66 + bLane0 * 2 + 0]       = BR[0];         \
        Bsm[(BUF) * 1056 + bnf * 66 + bLane0 * 2 + 1]       = BR[1];         \
        Bsm[(BUF) * 1056 + bnf * 66 + (bLane0 + 4) * 2 + 0] = BR[2];         \
        Bsm[(BUF) * 1056 + bnf * 66 + (bLane0 + 4) * 2 + 1] = BR[3];         \
    }
#define EP_CONSUME(BUF, CH)                                                  \
    {                                                                        \
        unsigned af[4][4], bf[4][2];                                         \
        _Pragma("unroll")                                                    \
        for (int mf = 0; mf < 4; mf++) {                                     \
            uint4 t = *(const uint4*)&Asm[(CH) * 1024 +                      \
                                          (wm * 4 + mf) * 128 + lphys * 4];  \
            af[mf][0] = t.x; af[mf][1] = t.y;                                \
            af[mf][2] = t.z; af[mf][3] = t.w;                                \
        }                                                                    \
        _Pragma("unroll")                                                    \
        for (int nf = 0; nf < 4; nf++) {                                     \
            uint2 t = *(const uint2*)&Bsm[(BUF) * 1056 +                     \
                                          (wn * 4 + nf) * 66 + lane * 2];    \
            bf[nf][0] = t.x; bf[nf][1] = t.y;                                \
        }                                                                    \
        _Pragma("unroll")                                                    \
        for (int mf = 0; mf < 4; mf++)                                       \
            _Pragma("unroll")                                                \
            for (int nf = 0; nf < 4; nf++)                                   \
                mma_f16_k16(acc[mf][nf], af[mf], bf[nf]);                    \
    }

        EP_LOADB(0, bS0);
        EP_STOREB(0, bS0);
        EP_LOADB(1, bS1);
        __syncthreads();
        int it = 0;
        for (;;) {
            if (it + 2 < 13) EP_LOADB(it + 2, bS0);
            EP_CONSUME(0, it);
            if (++it >= 13) break;
            EP_STOREB(1, bS1);
            __syncthreads();
            if (it + 2 < 13) EP_LOADB(it + 2, bS1);
            EP_CONSUME(1, it);
            if (++it >= 13) break;
            EP_STOREB(0, bS0);
            __syncthreads();
        }
#undef EP_LOADB
#undef EP_STOREB
#undef EP_CONSUME

#pragma unroll
        for (int mf = 0; mf < 4; mf++) {
#pragma unroll
            for (int nf = 0; nf < 4; nf++) {
                int row = m0 + wm * 64 + mf * 16 + (lane >> 2);
                int cc  = n0 + wn * 32 + nf * 8 + ((lane & 3) << 1);
                if (cc >= 1400) continue;
                __half* p = C + (size_t)row * CPITCH + cc;
                if (row < M)
                    store2(p, acc[mf][nf][0], acc[mf][nf][1]);
                if (row + 8 < M)
                    store2(p + (size_t)8 * CPITCH,
                           acc[mf][nf][2], acc[mf][nf][3]);
            }
        }
        __syncthreads();
    }
}

// =========================================================================
// fp16 tensor-core GEMM (fp32 accum): C = A(MxK,row) @ B(KxN,row)
// MODE 0: store. MODE 1: red.global. MODE 2: relu(acc*epiG+epiB).
// =========================================================================
template <class AT, class BT, class CT, int MODE>
__global__ void __launch_bounds__(256, 2) hmma_gemm_k(
    const AT* __restrict__ A, const BT* __restrict__ B,
    CT* __restrict__ C, int M, int N, int K,
    int lda, int ldb, int ldc, float alpha, int kChunk,
    const float* __restrict__ epiG, const float* __restrict__ epiB)
{
    __shared__ __align__(16) unsigned As[2][1024];
    __shared__ __align__(16) unsigned Bs[2][1056];

    const int tid  = threadIdx.x;
    const int lane = tid & 31;
    const int warp = tid >> 5;
    const int wm = warp >> 2;
    const int wn = warp & 3;
    const int m0 = blockIdx.y * 128;
    const int n0b = blockIdx.x * 128;

    const int kBegin = blockIdx.z * kChunk;
    const int kEnd   = min(kBegin + kChunk, K);
    const int iters  = (kEnd - kBegin) >> 4;
    const bool tail8 = ((kEnd - kBegin) & 8) != 0;

    const int am    = tid >> 1;
    const int khalf = tid & 1;
    const bool aVal = (m0 + am) < M;
    const AT* Ap = A + (size_t)(m0 + am) * lda + kBegin + khalf * 8;
    const int amf  = am >> 4;
    const int ar   = am & 15;
    const int arl  = ar & 7;
    const int aReg = (khalf << 1) | (ar >> 3);

    const int bkp = (tid >> 6) & 3;
    const int bn0 = (tid & 63) << 1;
    const bool bVal = (n0b + bn0) < N;
    const BT* Bp = B + (size_t)(kBegin + 2 * bkp) * ldb + n0b + bn0;
    const int bnf = bn0 >> 3;
    const int bLane0 = (bn0 & 7) * 4 + bkp;

    float acc[4][4][4];
#pragma unroll
    for (int i = 0; i < 4; i++)
#pragma unroll
        for (int j = 0; j < 4; j++)
#pragma unroll
            for (int q = 0; q < 4; q++) acc[i][j][q] = 0.f;

    uint4 aS0, aS1;
    unsigned bS0[4], bS1[4];
    const int lphys = lane ^ ((lane >> 3) & 3);

#define LOADR(IT, AR, BR)                                                    \
    {                                                                        \
        AR = aVal ? ldA8(Ap + ((IT) << 4)) : make_uint4(0u, 0u, 0u, 0u);     \
        if (bVal) loadBfrag(Bp + (size_t)((IT) << 4) * ldb, ldb, BR);        \
        else { BR[0] = BR[1] = BR[2] = BR[3] = 0u; }                         \
    }
#define STORER(BUF, AR, BR)                                                  \
    {                                                                        \
        unsigned aw[4] = {AR.x, AR.y, AR.z, AR.w};                           \
        _Pragma("unroll")                                                    \
        for (int jj = 0; jj < 4; jj++) {                                     \
            int c_   = arl * 4 + jj;                                         \
            int phys = c_ ^ ((c_ >> 3) & 3);                                 \
            As[BUF][amf * 128 + phys * 4 + aReg] = aw[jj];                   \
        }                                                                    \
        Bs[BUF][bnf * 66 + bLane0 * 2 + 0]       = BR[0];                    \
        Bs[BUF][bnf * 66 + bLane0 * 2 + 1]       = BR[1];                    \
        Bs[BUF][bnf * 66 + (bLane0 + 4) * 2 + 0] = BR[2];                    \
        Bs[BUF][bnf * 66 + (bLane0 + 4) * 2 + 1] = BR[3];                    \
    }
#define CONSUME(BUF)                                                         \
    {                                                                        \
        unsigned af[4][4], bf[4][2];                                         \
        _Pragma("unroll")                                                    \
        for (int mf = 0; mf < 4; mf++) {                                     \
            uint4 t = *(const uint4*)&As[BUF][(wm * 4 + mf) * 128 + lphys * 4]; \
            af[mf][0] = t.x; af[mf][1] = t.y; af[mf][2] = t.z; af[mf][3] = t.w; \
        }                                                                    \
        _Pragma("unroll")                                                    \
        for (int nf = 0; nf < 4; nf++) {                                     \
            uint2 t = *(const uint2*)&Bs[BUF][(wn * 4 + nf) * 66 + lane * 2]; \
            bf[nf][0] = t.x; bf[nf][1] = t.y;                                \
        }                                                                    \
        _Pragma("unroll")                                                    \
        for (int mf = 0; mf < 4; mf++)                                       \
            _Pragma("unroll")                                                \
            for (int nf = 0; nf < 4; nf++)                                   \
                mma_f16_k16(acc[mf][nf], af[mf], bf[nf]);                    \
    }

    if (iters > 0) {
        LOADR(0, aS0, bS0);
        STORER(0, aS0, bS0);
        if (iters > 1) LOADR(1, aS1, bS1);
        __syncthreads();
        int it = 0;
        for (;;) {
            if (it + 2 < iters) LOADR(it + 2, aS0, bS0);
            CONSUME(0);
            if (++it >= iters) break;
            STORER(1, aS1, bS1);
            __syncthreads();
            if (it + 2 < iters) LOADR(it + 2, aS1, bS1);
            CONSUME(1);
            if (++it >= iters) break;
            STORER(0, aS0, bS0);
            __syncthreads();
        }
    }
#undef LOADR
#undef STORER
#undef CONSUME

    if (tail8) {
        const int kT = kEnd - 8;
        const int kOff = kT + 2 * (lane & 3);
        unsigned bt[4];
#pragma unroll
        for (int nf = 0; nf < 4; nf++) {
            int col = n0b + wn * 32 + nf * 8 + (lane >> 2);
            float v0 = 0.f, v1 = 0.f;
            if (col < N) {
                v0 = ldS(B + (size_t)kOff * ldb + col);
                v1 = ldS(B + (size_t)(kOff + 1) * ldb + col);
            }
            bt[nf] = pack2(v0, v1);
        }
#pragma unroll
        for (int mf = 0; mf < 4; mf++) {
            int r0 = m0 + wm * 64 + mf * 16 + (lane >> 2);
            unsigned at[2];
            at[0] = (r0 < M)     ? ldA2(A + (size_t)r0 * lda + kOff)       : 0u;
            at[1] = (r0 + 8 < M) ? ldA2(A + (size_t)(r0 + 8) * lda + kOff) : 0u;
#pragma unroll
            for (int nf = 0; nf < 4; nf++)
                mma_f16_k8(acc[mf][nf], at, bt[nf]);
        }
    }

#pragma unroll
    for (int mf = 0; mf < 4; mf++) {
#pragma unroll
        for (int nf = 0; nf < 4; nf++) {
            int row = m0 + wm * 64 + mf * 16 + (lane >> 2);
            int col = n0b + wn * 32 + nf * 8 + ((lane & 3) << 1);
            if (col >= N) continue;
            CT* p = C + (size_t)row * ldc + col;
            float g0 = 0.f, g1 = 0.f, bb0 = 0.f, bb1 = 0.f;
            if (MODE == 2) {
                g0 = epiG[col]; g1 = epiG[col + 1];
                bb0 = epiB[col]; bb1 = epiB[col + 1];
            }
            if (row < M) {
                if (MODE == 1)
                    red2((float*)(void*)p,
                         alpha * acc[mf][nf][0], alpha * acc[mf][nf][1]);
                else if (MODE == 2)
                    store2(p, fmaxf(acc[mf][nf][0] * g0 + bb0, 0.f),
                              fmaxf(acc[mf][nf][1] * g1 + bb1, 0.f));
                else
                    store2(p, alpha * acc[mf][nf][0], alpha * acc[mf][nf][1]);
            }
            if (row + 8 < M) {
                CT* q = p + (size_t)8 * ldc;
                if (MODE == 1)
                    red2((float*)(void*)q,
                         alpha * acc[mf][nf][2], alpha * acc[mf][nf][3]);
                else if (MODE == 2)
                    store2(q, fmaxf(acc[mf][nf][2] * g0 + bb0, 0.f),
                              fmaxf(acc[mf][nf][3] * g1 + bb1, 0.f));
                else
                    store2(q, alpha * acc[mf][nf][2], alpha * acc[mf][nf][3]);
            }
        }
    }
}

// ---------------- SIMT SGEMM (exact fp32) for the weight precompute ------
template <bool ATOMIC>
__global__ void __launch_bounds__(256) sgemm_k(
    const float* __restrict__ A, const float* __restrict__ B,
    float* __restrict__ C, int M, int Ncols, int K,
    int lda, int ldb, int ldc, float alpha, int kChunk)
{
    __shared__ float As[8][128];
    __shared__ float Bs[8][128];

    const int tid = threadIdx.x;
    const int tx = tid & 15;
    const int ty = tid >> 4;
    const int m0 = blockIdx.y * 128;
    const int n0 = blockIdx.x * 128;

    int kBegin = blockIdx.z * kChunk;
    int kEnd = kBegin + kChunk;
    if (kEnd > K) kEnd = K;

    const int aRow = tid >> 1;
    const int aK4  = (tid & 1) << 2;
    const int bRow = tid >> 5;
    const int bCol = (tid & 31) << 2;

    float acc[8][8];
#pragma unroll
    for (int i = 0; i < 8; i++)
#pragma unroll
        for (int j = 0; j < 8; j++) acc[i][j] = 0.f;

    for (int k0 = kBegin; k0 < kEnd; k0 += 8) {
        float4 av = make_float4(0.f, 0.f, 0.f, 0.f);
        if (m0 + aRow < M)
            av = *(const float4*)(A + (size_t)(m0 + aRow) * lda + (k0 + aK4));
        As[aK4 + 0][aRow] = av.x;
        As[aK4 + 1][aRow] = av.y;
        As[aK4 + 2][aRow] = av.z;
        As[aK4 + 3][aRow] = av.w;

        float4 bv = make_float4(0.f, 0.f, 0.f, 0.f);
        if (n0 + bCol < Ncols)
            bv = *(const float4*)(B + (size_t)(k0 + bRow) * ldb + (n0 + bCol));
        *(float4*)&Bs[bRow][bCol] = bv;

        __syncthreads();
#pragma unroll
        for (int kk = 0; kk < 8; kk++) {
            float ar[8], br[8];
#pragma unroll
            for (int i = 0; i < 8; i++) ar[i] = As[kk][ty * 8 + i];
#pragma unroll
            for (int j = 0; j < 8; j++) br[j] = Bs[kk][tx * 8 + j];
#pragma unroll
            for (int i = 0; i < 8; i++)
#pragma unroll
                for (int j = 0; j < 8; j++)
                    acc[i][j] = fmaf(ar[i], br[j], acc[i][j]);
        }
        __syncthreads();
    }

#pragma unroll
    for (int i = 0; i < 8; i++) {
        int m = m0 + ty * 8 + i;
        if (m >= M) continue;
        if (ATOMIC) {
#pragma unroll
            for (int jj = 0; jj < 8; jj += 2) {
                int n = n0 + tx * 8 + jj;
                if (n < Ncols)
                    red2(C + (size_t)m * ldc + n,
                         alpha * acc[i][jj], alpha * acc[i][jj + 1]);
            }
        } else {
#pragma unroll
            for (int jj = 0; jj < 8; jj += 4) {
                int n = n0 + tx * 8 + jj;
                if (n < Ncols) {
                    float4 v = make_float4(alpha * acc[i][jj + 0],
                                           alpha * acc[i][jj + 1],
                                           alpha * acc[i][jj + 2],
                                           alpha * acc[i][jj + 3]);
                    *(float4*)(C + (size_t)m * ldc + n) = v;
                }
            }
        }
    }
}

// ---------------- merged prep: f2h(E) | permfcw | f2h(R) | convprep ------
__global__ void __launch_bounds__(256) prep_k(
    const float* __restrict__ E, const float* __restrict__ R,
    const float* __restrict__ fc_w,
    const float* __restrict__ conv_w, const float* __restrict__ conv_b,
    const float* __restrict__ bn1_g, const float* __restrict__ bn1_b,
    int n4e, int n4r, int bA, int bB, int bC)
{
    int b = blockIdx.x;
    int t = threadIdx.x;
    if (b < bA) {
        int i = b * 256 + t;
        if (i < n4e) {
            float4 v = ((const float4*)E)[i];
            uint2 o;
            o.x = pack2(v.x, v.y);
            o.y = pack2(v.z, v.w);
            ((uint2*)g_Eh)[i] = o;
        }
    } else if (b < bA + bB) {
        int idx = (b - bA) * 256 + t;
        if (idx < FEATK * 50) {
            int r = idx / 50;
            int c = idx - r * 50;
            int p  = r / 200;
            int nf = r - p * 200;
            float4 v = *(const float4*)(fc_w + ((size_t)nf * 198 + p) * 200 + c * 4);
            uint2 o;
            o.x = pack2(v.x, v.y);
            o.y = pack2(v.z, v.w);
            *(uint2*)(g_fcwh + (size_t)r * 200 + c * 4) = o;
        }
    } else if (b < bA + bB + bC) {
        int i = (b - bA - bB) * 256 + t;
        if (i < n4r) {
            float4 v = ((const float4*)R)[i];
            uint2 o;
            o.x = pack2(v.x, v.y);
            o.y = pack2(v.z, v.w);
            ((uint2*)g_Rh)[i] = o;
        }
    } else {
        int idx = (b - bA - bB - bC) * 256 + t;
        if (idx < 32 * 200) {
            int k  = idx / 200;
            int nf = idx - k * 200;
            float v = (k < 21) ? conv_w[nf * 21 + k] : 0.f;
            g_convW[k * 200 + nf] = __float2half(v);
        }
        if (idx < 256) {
            if (idx < 200) {
                float g = bn1_g[idx] * BNS;
                g_epiG[idx] = g;
                g_epiB[idx] = conv_b[idx] * g + bn1_b[idx];
            } else {
                g_epiG[idx] = 0.f;
                g_epiB[idx] = 0.f;
            }
        }
    }
}

// ---------------- merged comb (200x1400 fp16) + Wcat (200x400 fp16) ------
__global__ void __launch_bounds__(256) combwcat_k(
    const float* __restrict__ E, const float* __restrict__ w_addpos,
    const float* __restrict__ w_rel, int ent, int bComb)
{
    int b = blockIdx.x;
    int t = threadIdx.x;
    if (b < bComb) {
        int idx = b * 256 + t;
        if (idx < 200 * 1400) {
            int i = idx / 1400;
            int c = idx - i * 1400;
            float v;
            if (c < 1200) {
                int k = c / 200;
                int j = c - k * 200;
                v = 0.5f * E[(size_t)(ent + k) * DD + i] *
                    g_U[(size_t)(k * 200 + i) * 200 + j];
            } else {
                v = w_addpos[(size_t)(200 + i) * 200 + (c - 1200)];
            }
            g_combh[(size_t)i * CPITCH + c] = __float2half(v);
        }
    } else {
        int idx = (b - bComb) * 256 + t;
        if (idx < 200 * 400) {
            int i = idx / 400;
            int c = idx - i * 400;
            float v = (c < 200) ? 0.5f * g_T[i * 200 + c]
                                : w_rel[(size_t)i * 200 + (c - 200)];
            g_Wcat[idx] = __float2half(v);
        }
    }
}

// ---------------- hembW[h] = RO[he0,0:200] + sum_k EP[he_k+1, k*200:] ----
__global__ void hembw_k(const int* __restrict__ he, int H)
{
    int t = blockIdx.x * 256 + threadIdx.x;
    int h = t / 50;
    int c = t - h * 50;
    if (h >= H) return;
    const int* row = he + (size_t)h * 7;
    int r = row[0];
    float4 acc = *(const float4*)(g_RO + (size_t)r * 400 + c * 4);
#pragma unroll
    for (int k = 0; k < 6; k++) {
        int e = row[1 + k];
        float4 v = ld4(g_EP + (size_t)e * CPITCH + k * 200 + c * 4);
        acc.x += v.x; acc.y += v.y; acc.z += v.z; acc.w += v.w;
    }
    __half* dst = g_hembW + (size_t)h * 200 + c * 4;
    ((__half2*)dst)[0] = __floats2half2_rn(acc.x, acc.y);
    ((__half2*)dst)[1] = __floats2half2_rn(acc.z, acc.w);
}

// ---------------- per-edge scatter (fp16x2 vector RED) --------------------
__global__ void edge_k(const int* __restrict__ ei,
                       const int* __restrict__ et, int NEdge)
{
    int t = blockIdx.x * 256 + threadIdx.x;
    int e = t / 25;
    int c = t - e * 25;
    if (e >= NEdge) return;
    int seg  = ei[e];
    int gidx = ei[NEdge + e];
    int h    = et[e];
    uint4 ua = *(const uint4*)(g_hembW + (size_t)h * 200 + c * 8);
    uint4 ub = *(const uint4*)(g_EP + (size_t)gidx * CPITCH + 1200 + c * 8);
    unsigned r[4];
#pragma unroll
    for (int j = 0; j < 4; j++) {
        __half2 x = ((__half2*)&ua)[j];
        __half2 y = ((__half2*)&ub)[j];
        __half2 s = __hadd2(x, y);
        r[j] = *(unsigned*)&s;
    }
    __half* p = g_agg + (size_t)seg * 200 + c * 8;
    asm volatile("red.global.add.noftz.v4.f16x2 [%0], {%1, %2, %3, %4};"
                 :: "l"(p), "r"(r[0]), "r"(r[1]), "r"(r[2]), "r"(r[3])
                 : "memory");
}

// ---------------- build im2col X rows (fp16), outE computed on the fly ---
struct IdxPtrs { const int* p[6]; };

__global__ void __launch_bounds__(256) buildX_k(
    const float* __restrict__ ms, const int* __restrict__ r_idx, IdxPtrs ip,
    const float* __restrict__ bn0_g, const float* __restrict__ bn0_b,
    const float* __restrict__ E,
    const float* __restrict__ gmp, const float* __restrict__ bmp,
    int ent)
{
    __shared__ float xs[7][204];
    __shared__ float pos[6][200];

    int b = blockIdx.x;
    int t = threadIdx.x;

    // qpos rows ent..ent+5: tanh(bn(0.5*(agg+E)))  (L2-hot broadcast reads)
    for (int idx = t; idx < 1200; idx += 256) {
        int k = idx / 200;
        int d = idx - k * 200;
        size_t off = (size_t)(ent + k) * 200 + d;
        float a = __half2float(g_agg[off]);
        float e = E[off];
        pos[k][d] = tanhf(0.5f * (a + e) * (gmp[d] * BNS) + bmp[d]);
    }
    __syncthreads();

    float g0 = bn0_g[0] * BNS;
    float b0 = bn0_b[0];
    int ri = r_idx[b];

    for (int idx = t; idx < 1400; idx += 256) {
        int i = idx / 200;
        int d = idx - i * 200;
        float v;
        if (i == 0) {
            v = g_RO[(size_t)ri * 400 + 200 + d];
        } else {
            int k = i - 1;
            int eidx = ip.p[k][b];
            size_t off = (size_t)eidx * 200 + d;
            float a = __half2float(g_agg[off]);
            float e = E[off];
            float ve = tanhf(0.5f * (a + e) * (gmp[d] * BNS) + bmp[d]);
            v = ve * pos[k][d] * ms[b * 6 + k];
        }
        xs[i][d] = v * g0 + b0;
    }
    __syncthreads();

    if (t < 198) {
        int p = t;
        unsigned w[16];
        float x[7][3];
#pragma unroll
        for (int i = 0; i < 7; i++)
#pragma unroll
            for (int q = 0; q < 3; q++) x[i][q] = xs[i][p + q];
        w[0]  = pack2(x[0][0], x[0][1]);
        w[1]  = pack2(x[0][2], x[1][0]);
        w[2]  = pack2(x[1][1], x[1][2]);
        w[3]  = pack2(x[2][0], x[2][1]);
        w[4]  = pack2(x[2][2], x[3][0]);
        w[5]  = pack2(x[3][1], x[3][2]);
        w[6]  = pack2(x[4][0], x[4][1]);
        w[7]  = pack2(x[4][2], x[5][0]);
        w[8]  = pack2(x[5][1], x[5][2]);
        w[9]  = pack2(x[6][0], x[6][1]);
        w[10] = pack2(x[6][2], 0.f);
#pragma unroll
        for (int q = 11; q < 16; q++) w[q] = 0u;
        uint4* dst = (uint4*)(g_X + ((size_t)b * 198 + p) * 32);
        dst[0] = make_uint4(w[0], w[1], w[2], w[3]);
        dst[1] = make_uint4(w[4], w[5], w[6], w[7]);
        dst[2] = make_uint4(w[8], w[9], w[10], w[11]);
        dst[3] = make_uint4(w[12], w[13], w[14], w[15]);
    }
}

// ---------------- final: relu(bn2(fc + bias)) row-sum -> out[b] ----------
__global__ void final_k(const float* __restrict__ fc_b,
                        const float* __restrict__ g,
                        const float* __restrict__ bb,
                        float* __restrict__ out, int B)
{
    int gt = blockIdx.x * 256 + threadIdx.x;
    int wb = gt >> 5;
    int lane = gt & 31;
    if (wb >= B) return;
    float s = 0.f;
    for (int d = lane; d < 200; d += 32) {
        float v = (g_FCACC[(size_t)wb * 200 + d] + fc_b[d]) * (g[d] * BNS) + bb[d];
        s += fmaxf(v, 0.f);
    }
#pragma unroll
    for (int o = 16; o; o >>= 1) s += __shfl_down_sync(0xffffffffu, s, o);
    if (lane == 0) out[wb] = s;
}

// ---------------- host orchestration ------------------------------------
extern "C" void kernel_launch(void* const* d_in, const int* in_sizes, int n_in,
                              void* d_out, int out_size)
{
    const float* E          = (const float*)d_in[0];
    const float* R          = (const float*)d_in[1];
    const float* w_alle     = (const float*)d_in[2];
    const float* w_addpos   = (const float*)d_in[3];
    const float* w_alleandr = (const float*)d_in[4];
    const float* w_rel      = (const float*)d_in[5];
    const float* conv_w     = (const float*)d_in[6];
    const float* conv_b     = (const float*)d_in[7];
    const float* fc_w       = (const float*)d_in[8];
    const float* fc_b       = (const float*)d_in[9];
    const float* bnmp_g     = (const float*)d_in[10];
    const float* bnmp_b     = (const float*)d_in[11];
    const float* bn0_g      = (const float*)d_in[12];
    const float* bn0_b      = (const float*)d_in[13];
    const float* bn1_g      = (const float*)d_in[14];
    const float* bn1_b      = (const float*)d_in[15];
    const float* bn2_g      = (const float*)d_in[16];
    const float* bn2_b      = (const float*)d_in[17];
    const float* ms         = (const float*)d_in[18];
    const int*   hyperedge  = (const int*)d_in[19];
    const int*   edge_index = (const int*)d_in[20];
    const int*   edge_type  = (const int*)d_in[21];
    const int*   r_idx      = (const int*)d_in[22];
    IdxPtrs ip;
    for (int k = 0; k < 6; k++) ip.p[k] = (const int*)d_in[23 + k];

    const int Ntot  = in_sizes[0] / DD;   // 50006
    const int ent   = Ntot - 6;
    const int NR    = in_sizes[1] / DD;   // 2000
    const int H     = in_sizes[19] / 7;   // 100000
    const int NEdge = in_sizes[21];       // 600000
    const int Bsz   = in_sizes[22];       // 2048

    float *pT, *pU, *pRO, *pFC, *pG, *pB;
    __half *pComb, *pWcat, *pEh, *pRh, *pFcw, *pEP, *pY, *pX, *pCW, *pAgg;
    cudaGetSymbolAddress((void**)&pT,    g_T);
    cudaGetSymbolAddress((void**)&pU,    g_U);
    cudaGetSymbolAddress((void**)&pComb, g_combh);
    cudaGetSymbolAddress((void**)&pWcat, g_Wcat);
    cudaGetSymbolAddress((void**)&pRO,   g_RO);
    cudaGetSymbolAddress((void**)&pEh,   g_Eh);
    cudaGetSymbolAddress((void**)&pRh,   g_Rh);
    cudaGetSymbolAddress((void**)&pFcw,  g_fcwh);
    cudaGetSymbolAddress((void**)&pEP,   g_EP);
    cudaGetSymbolAddress((void**)&pAgg,  g_agg);
    cudaGetSymbolAddress((void**)&pY,    g_Y);
    cudaGetSymbolAddress((void**)&pX,    g_X);
    cudaGetSymbolAddress((void**)&pCW,   g_convW);
    cudaGetSymbolAddress((void**)&pG,    g_epiG);
    cudaGetSymbolAddress((void**)&pB,    g_epiB);
    cudaGetSymbolAddress((void**)&pFC,   g_FCACC);

    cudaFuncSetAttribute(ep_gemm_k,
                         cudaFuncAttributeMaxDynamicSharedMemorySize,
                         EP_SMEM);

    cudaMemsetAsync(pT,   0, 200 * 200 * sizeof(float), 0);
    cudaMemsetAsync(pU,   0, 1200 * 200 * sizeof(float), 0);
    cudaMemsetAsync(pAgg, 0, (size_t)Ntot * 200 * sizeof(__half), 0);
    cudaMemsetAsync(pFC,  0, (size_t)Bsz * 200 * sizeof(float), 0);

    // merged prep: f2h(E) | permfcw | f2h(R) | convprep
    {
        int n4e = Ntot * DD / 4;
        int n4r = NR * DD / 4;
        int bA = (n4e + 255) / 256;
        int bB = (FEATK * 50 + 255) / 256;
        int bC = (n4r + 255) / 256;
        int bD = (32 * 200 + 255) / 256;
        prep_k<<<bA + bB + bC + bD, 256>>>(E, R, fc_w, conv_w, conv_b,
                                           bn1_g, bn1_b, n4e, n4r, bA, bB, bC);
    }

    // T = w_alleandr @ w_addpos_top  (exact fp32, split-K)
    sgemm_k<true><<<dim3(2, 2, 13), 256>>>(w_alleandr, w_addpos, pT,
                                           200, 200, 200, 200, 200, 200, 1.f, 16);
    // U = w_alle @ T  (exact fp32)
    sgemm_k<true><<<dim3(2, 10, 5), 256>>>(w_alle, pT, pU,
                                           1200, 200, 200, 200, 200, 200, 1.f, 40);
    // merged comb + Wcat (fp16)
    {
        int bComb = (200 * 1400 + 255) / 256;
        int bW    = (200 * 400 + 255) / 256;
        combwcat_k<<<bComb + bW, 256>>>(E, w_addpos, w_rel, ent, bComb);
    }
    // RO = Rh @ Wcat  (fp16 MMA, fp32 out; cols 0..199 = RW, 200..399 = outR)
    hmma_gemm_k<__half, __half, float, 0>
        <<<dim3(4, (NR + 127) / 128, 1), 256>>>(
        pRh, pWcat, pRO, NR, 400, 200, 200, 400, 400, 1.f, 200,
        nullptr, nullptr);
    // EP = Eh @ comb  (A-resident fp16 MMA)
    ep_gemm_k<<<dim3(2, (Ntot + 127) / 128, 1), 256, EP_SMEM>>>(
        pEh, pComb, pEP, Ntot);
    // hembW: gather-sum per hyperedge (fp32 accum, fp16 store)
    hembw_k<<<(H * 50 + 255) / 256, 256>>>(hyperedge, H);
    // per-edge scatter (fp16 gathers, fp16x2 vector RED)
    edge_k<<<(NEdge * 25 + 255) / 256, 256>>>(edge_index, edge_type, NEdge);
    // im2col X (bn0 fused; outE computed on the fly — oute_k eliminated)
    buildX_k<<<Bsz, 256>>>(ms, r_idx, ip, bn0_g, bn0_b, E,
                           bnmp_g, bnmp_b, ent);
    // Y = relu(conv(X) * g1 + bias)  (fp16 MMA, fused epilogue)
    hmma_gemm_k<__half, __half, __half, 2>
        <<<dim3(2, (Bsz * 198) / 128, 1), 256>>>(
        pX, pCW, pY, Bsz * 198, 200, 32, 32, 200, 200, 1.f, 32, pG, pB);
    // FCACC += Y @ fcwh  (fp16 MMA, split-K 25 x 1584)
    hmma_gemm_k<__half, __half, float, 1>
        <<<dim3(2, (Bsz + 127) / 128, 25), 256>>>(
        pY, pFcw, pFC, Bsz, 200, FEATK, FEATK, 200, 200, 1.f, 1584,
        nullptr, nullptr);
    // out[b] = sum_d relu(bn2(FCACC + fc_b))
    final_k<<<(Bsz * 32 + 255) / 256, 256>>>(fc_b, bn2_g, bn2_b,
                                             (float*)d_out, Bsz);
}